// round 1
// baseline (speedup 1.0000x reference)
#include <cuda_runtime.h>
#include <cstdint>

// Problem constants (fixed shapes per reference)
#define BATCH 64
#define HH 512
#define WW 512
#define WIN 11
#define C1F 0.0001f   // (0.01)^2
#define C2F 0.0009f   // (0.03)^2

// Tiling
#define TILE_W 256          // columns per CTA
#define TILE_H 32           // output rows per CTA
#define NCOLT (WW / TILE_W) // 2
#define NROWT (HH / TILE_H) // 16
#define NPART (BATCH * NCOLT * NROWT) // 2048

// SMEM layout (floats)
//  ring: 11 slots x 5 fields x TILE_W
//  xrow/yrow: TILE_W + 10 halo (padded to 272)
#define RING_F (11 * 5 * TILE_W)
#define ROW_F  272
#define SMEM_FLOATS (RING_F + 2 * ROW_F + 16)
#define SMEM_BYTES (SMEM_FLOATS * 4)

__device__ float g_partials[NPART];

__global__ __launch_bounds__(TILE_W, 1)
void ssim_map_kernel(const float* __restrict__ x,
                     const float* __restrict__ y,
                     const float* __restrict__ win)
{
    extern __shared__ float smem[];
    float* ring = smem;                 // [slot*5 + field][TILE_W]
    float* xrow = ring + RING_F;        // [ROW_F]
    float* yrow = xrow + ROW_F;         // [ROW_F]
    float* gwin = yrow + ROW_F;         // [11]

    const int t  = threadIdx.x;
    const int ct = blockIdx.x;          // col tile
    const int rt = blockIdx.y;          // row tile
    const int b  = blockIdx.z;          // image

    const int c0 = ct * TILE_W;
    const int r0 = rt * TILE_H;
    const float* xb = x + (size_t)b * HH * WW;
    const float* yb = y + (size_t)b * HH * WW;

    // Recover separable 1D Gaussian: g[i] = sum_j w2d[i][j] (since sum(g)=1)
    if (t < WIN) {
        float s = 0.f;
        #pragma unroll
        for (int j = 0; j < WIN; ++j) s += win[t * WIN + j];
        gwin[t] = s;
    }
    __syncthreads();

    float g[WIN];
    #pragma unroll
    for (int i = 0; i < WIN; ++i) g[i] = gwin[i];

    float acc = 0.f;
    int slot = 0;

    for (int pr = 0; pr < TILE_H + 10; ++pr) {
        const int r_in = r0 - 5 + pr;
        const bool rv = (r_in >= 0) && (r_in < HH);

        __syncthreads();  // prior iteration's ring/xrow reads complete

        // ---- stage input row with +-5 column halo (zero padded) ----
        {
            int gc = c0 - 5 + t;
            bool cv = rv && (gc >= 0) && (gc < WW);
            size_t off = (size_t)r_in * WW + gc;
            xrow[t] = cv ? xb[off] : 0.f;
            yrow[t] = cv ? yb[off] : 0.f;
            if (t < 10) {
                int j = TILE_W + t;
                int gc2 = c0 - 5 + j;
                bool cv2 = rv && (gc2 < WW);   // gc2 >= 0 always
                size_t off2 = (size_t)r_in * WW + gc2;
                xrow[j] = cv2 ? xb[off2] : 0.f;
                yrow[j] = cv2 ? yb[off2] : 0.f;
            }
        }
        __syncthreads();

        // ---- horizontal 11-tap conv of 5 fields ----
        {
            float hx = 0.f, hy = 0.f, hxx = 0.f, hyy = 0.f, hxy = 0.f;
            #pragma unroll
            for (int j = 0; j < WIN; ++j) {
                float a = xrow[t + j];
                float bb = yrow[t + j];
                float gg = g[j];
                hx  += gg * a;
                hy  += gg * bb;
                hxx += gg * (a * a);
                hyy += gg * (bb * bb);
                hxy += gg * (a * bb);
            }
            float* rs = ring + (slot * 5) * TILE_W + t;
            rs[0 * TILE_W] = hx;
            rs[1 * TILE_W] = hy;
            rs[2 * TILE_W] = hxx;
            rs[3 * TILE_W] = hyy;
            rs[4 * TILE_W] = hxy;
        }
        __syncthreads();

        // ---- vertical 11-tap conv + SSIM once ring is full ----
        if (pr >= 10) {
            float mx = 0.f, my = 0.f, sxx = 0.f, syy = 0.f, sxy = 0.f;
            int s = slot + 1; if (s >= WIN) s = 0;   // oldest slot
            #pragma unroll
            for (int k = 0; k < WIN; ++k) {
                const float* rr = ring + (s * 5) * TILE_W + t;
                float gk = g[k];
                mx  += gk * rr[0 * TILE_W];
                my  += gk * rr[1 * TILE_W];
                sxx += gk * rr[2 * TILE_W];
                syy += gk * rr[3 * TILE_W];
                sxy += gk * rr[4 * TILE_W];
                if (++s >= WIN) s = 0;
            }
            float mx2 = mx * mx, my2 = my * my, mxy = mx * my;
            float vx = sxx - mx2, vy = syy - my2, vxy = sxy - mxy;
            float num = (2.f * mxy + C1F) * (2.f * vxy + C2F);
            float den = (mx2 + my2 + C1F) * (vx + vy + C2F);
            acc += __fdividef(num, den);
        }

        if (++slot >= WIN) slot = 0;
    }

    // ---- block reduction (deterministic) ----
    __syncthreads();
    #pragma unroll
    for (int o = 16; o > 0; o >>= 1)
        acc += __shfl_down_sync(0xFFFFFFFFu, acc, o);
    const int warp = t >> 5;
    const int lane = t & 31;
    if (lane == 0) xrow[warp] = acc;
    __syncthreads();
    if (t == 0) {
        float s = 0.f;
        #pragma unroll
        for (int w = 0; w < TILE_W / 32; ++w) s += xrow[w];
        int pid = (b * NROWT + rt) * NCOLT + ct;
        g_partials[pid] = s;
    }
}

__global__ void ssim_reduce_kernel(float* __restrict__ out)
{
    __shared__ float s[512];
    int t = threadIdx.x;
    float v = g_partials[t] + g_partials[t + 512] +
              g_partials[t + 1024] + g_partials[t + 1536];
    s[t] = v;
    __syncthreads();
    #pragma unroll
    for (int o = 256; o > 0; o >>= 1) {
        if (t < o) s[t] += s[t + o];
        __syncthreads();
    }
    if (t == 0) out[0] = s[0] * (1.0f / ((float)BATCH * HH * WW));
}

extern "C" void kernel_launch(void* const* d_in, const int* in_sizes, int n_in,
                              void* d_out, int out_size)
{
    const float* x   = (const float*)d_in[0];
    const float* y   = (const float*)d_in[1];
    const float* win = (const float*)d_in[2];
    float* out = (float*)d_out;

    static bool attr_set = false;
    if (!attr_set) {
        cudaFuncSetAttribute(ssim_map_kernel,
                             cudaFuncAttributeMaxDynamicSharedMemorySize,
                             SMEM_BYTES);
        attr_set = true;
    }

    dim3 grid(NCOLT, NROWT, BATCH);
    ssim_map_kernel<<<grid, TILE_W, SMEM_BYTES>>>(x, y, win);
    ssim_reduce_kernel<<<1, 512>>>(out);
}

// round 3
// speedup vs baseline: 1.6813x; 1.6813x over previous
#include <cuda_runtime.h>
#include <cstdint>

#define BATCH 64
#define HH 512
#define WW 512
#define TILE_H 32
#define NROWT (HH / TILE_H)    // 16
#define NPART (BATCH * NROWT)  // 1024
#define DEPTH 8
#define ROWF 528               // 8 zero-halo + 512 + 8 zero-halo floats
#define NSTAGE (TILE_H + 10)   // 42 staged rows per tile

typedef unsigned long long u64;

__device__ float g_partials[NPART];

// ---- packed f32x2 helpers (Blackwell FFMA2 path, PTX-only) ----
__device__ __forceinline__ u64 pk2(float lo, float hi) {
    u64 r; asm("mov.b64 %0, {%1, %2};" : "=l"(r) : "f"(lo), "f"(hi)); return r;
}
__device__ __forceinline__ void upk2(u64 v, float& lo, float& hi) {
    asm("mov.b64 {%0, %1}, %2;" : "=f"(lo), "=f"(hi) : "l"(v));
}
__device__ __forceinline__ u64 f2mul(u64 a, u64 b) {
    u64 d; asm("mul.rn.f32x2 %0, %1, %2;" : "=l"(d) : "l"(a), "l"(b)); return d;
}
__device__ __forceinline__ u64 f2add(u64 a, u64 b) {
    u64 d; asm("add.rn.f32x2 %0, %1, %2;" : "=l"(d) : "l"(a), "l"(b)); return d;
}
__device__ __forceinline__ u64 f2fma(u64 a, u64 b, u64 c) {
    u64 d; asm("fma.rn.f32x2 %0, %1, %2, %3;" : "=l"(d) : "l"(a), "l"(b), "l"(c)); return d;
}

__global__ __launch_bounds__(256, 1)
void ssim_map_kernel(const float* __restrict__ x, const float* __restrict__ y,
                     const float* __restrict__ win)
{
    __shared__ float sbuf[DEPTH][2][ROWF];   // 33792 B row ring, fields x/y

    const int t  = threadIdx.x;
    const int rt = blockIdx.x;
    const int b  = blockIdx.y;
    const int r0 = rt * TILE_H;
    const float* xb = x + (size_t)b * HH * WW;
    const float* yb = y + (size_t)b * HH * WW;

    // zero the column halos once (8 slots * 2 fields * 16 floats = 256 = blockDim)
    {
        int slot = t >> 5, f = (t >> 4) & 1, k = t & 15;
        int pos = (k < 8) ? k : (512 + k);   // [0..7] and [520..527]
        sbuf[slot][f][pos] = 0.f;
    }

    // recover separable 1D taps: g[i] = sum_j w2d[i][j]  (sum g == 1), packed (g,g)
    u64 g2[11];
    #pragma unroll
    for (int i = 0; i < 11; ++i) {
        float s = 0.f;
        #pragma unroll
        for (int j = 0; j < 11; ++j) s += win[i * 11 + j];
        g2[i] = pk2(s, s);
    }

    const u64 HC1  = pk2(5e-5f, 5e-5f);     // C1/2
    const u64 HC2  = pk2(4.5e-4f, 4.5e-4f); // C2/2
    const u64 FC1  = pk2(1e-4f, 1e-4f);     // C1
    const u64 FC2  = pk2(9e-4f, 9e-4f);     // C2
    const u64 NEG1 = pk2(-1.f, -1.f);

    // ---- row fill: cp.async 8B per field; zeros for out-of-image rows ----
    auto fill_row = [&](int p) {
        int slot = p & 7;
        int r_in = r0 - 5 + p;
        float* dx = &sbuf[slot][0][8 + 2 * t];
        float* dy = &sbuf[slot][1][8 + 2 * t];
        if ((unsigned)r_in < (unsigned)HH) {
            const float* gx = xb + (size_t)r_in * WW + 2 * t;
            const float* gy = yb + (size_t)r_in * WW + 2 * t;
            unsigned sx = (unsigned)__cvta_generic_to_shared(dx);
            unsigned sy = (unsigned)__cvta_generic_to_shared(dy);
            asm volatile("cp.async.ca.shared.global [%0], [%1], 8;" :: "r"(sx), "l"(gx) : "memory");
            asm volatile("cp.async.ca.shared.global [%0], [%1], 8;" :: "r"(sy), "l"(gy) : "memory");
        } else {
            *(float2*)dx = make_float2(0.f, 0.f);
            *(float2*)dy = make_float2(0.f, 0.f);
        }
    };

    // prologue: prefetch rows 0..6, one commit group each
    #pragma unroll
    for (int p = 0; p < 7; ++p) {
        fill_row(p);
        asm volatile("cp.async.commit_group;" ::: "memory");
    }

    // register ring: 11 rows x 4 packed fields (mu_x, mu_y, x^2+y^2, x*y)
    u64 RX[11], RY[11], RS[11], RP[11];
    float acc = 0.f;

    for (int blk = 0; blk < 4; ++blk) {
        #pragma unroll
        for (int ph = 0; ph < 11; ++ph) {
            const int pr = blk * 11 + ph;
            if (pr < NSTAGE) {
                __syncthreads();                       // prior reads of reused slot done
                int pf = pr + 7;
                if (pf < NSTAGE) fill_row(pf);
                asm volatile("cp.async.commit_group;" ::: "memory");
                asm volatile("cp.async.wait_group 7;" ::: "memory");
                __syncthreads();                       // row pr visible to all

                // stage 14 floats per field into registers (aligned float2 loads)
                const float2* xv = (const float2*)sbuf[pr & 7][0] + (t + 1);
                const float2* yv = (const float2*)sbuf[pr & 7][1] + (t + 1);
                float xr[14], yr[14];
                #pragma unroll
                for (int i = 0; i < 7; ++i) {
                    float2 a = xv[i]; xr[2 * i] = a.x; xr[2 * i + 1] = a.y;
                    float2 c = yv[i]; yr[2 * i] = c.x; yr[2 * i + 1] = c.y;
                }

                // horizontal 11-tap conv, packed over column pair (2t, 2t+1)
                u64 hx = 0, hy = 0, hs = 0, hp = 0;
                #pragma unroll
                for (int j = 0; j < 11; ++j) {
                    u64 ax = pk2(xr[1 + j], xr[2 + j]);
                    u64 ay = pk2(yr[1 + j], yr[2 + j]);
                    hx = f2fma(g2[j], ax, hx);
                    hy = f2fma(g2[j], ay, hy);
                    u64 ss = f2mul(ax, ax);
                    ss = f2fma(ay, ay, ss);
                    hs = f2fma(g2[j], ss, hs);
                    u64 pp = f2mul(ax, ay);
                    hp = f2fma(g2[j], pp, hp);
                }
                RX[ph] = hx; RY[ph] = hy; RS[ph] = hs; RP[ph] = hp;

                // vertical 11-tap conv + SSIM once ring is warm
                if (pr >= 10) {
                    u64 mx = f2mul(g2[0], RX[(ph + 1) % 11]);
                    u64 my = f2mul(g2[0], RY[(ph + 1) % 11]);
                    u64 sp = f2mul(g2[0], RS[(ph + 1) % 11]);
                    u64 sx = f2mul(g2[0], RP[(ph + 1) % 11]);
                    #pragma unroll
                    for (int k = 1; k < 11; ++k) {
                        const int sl = (ph + 1 + k) % 11;
                        mx = f2fma(g2[k], RX[sl], mx);
                        my = f2fma(g2[k], RY[sl], my);
                        sp = f2fma(g2[k], RS[sl], sp);
                        sx = f2fma(g2[k], RP[sl], sx);
                    }
                    u64 mx2 = f2mul(mx, mx);
                    u64 my2 = f2mul(my, my);
                    u64 mxy = f2mul(mx, my);
                    u64 msq = f2add(mx2, my2);
                    u64 vp  = f2fma(msq, NEG1, sp);    // sigma_x^2 + sigma_y^2
                    u64 vxy = f2fma(mxy, NEG1, sx);    // sigma_xy
                    u64 t1  = f2add(mxy, HC1);
                    u64 t2  = f2add(vxy, HC2);
                    u64 num = f2mul(t1, t2);           // ssim = 4*num/den
                    u64 t3  = f2add(msq, FC1);
                    u64 t4  = f2add(vp,  FC2);
                    u64 den = f2mul(t3, t4);
                    float n0, n1, d0, d1;
                    upk2(num, n0, n1);
                    upk2(den, d0, d1);
                    acc += __fdividef(n0, d0) + __fdividef(n1, d1);
                }
            }
        }
    }

    // drain any in-flight async copies before reusing sbuf for the reduction
    asm volatile("cp.async.wait_group 0;" ::: "memory");

    // ---- deterministic block reduction ----
    #pragma unroll
    for (int o = 16; o; o >>= 1) acc += __shfl_down_sync(0xFFFFFFFFu, acc, o);
    __syncthreads();
    if ((t & 31) == 0) sbuf[0][0][t >> 5] = acc;
    __syncthreads();
    if (t == 0) {
        float s = 0.f;
        #pragma unroll
        for (int w = 0; w < 8; ++w) s += sbuf[0][0][w];
        g_partials[b * NROWT + rt] = s;
    }
}

__global__ void ssim_reduce_kernel(float* __restrict__ out)
{
    __shared__ float s[512];
    int t = threadIdx.x;
    s[t] = g_partials[t] + g_partials[t + 512];
    __syncthreads();
    #pragma unroll
    for (int o = 256; o; o >>= 1) {
        if (t < o) s[t] += s[t + o];
        __syncthreads();
    }
    // each accumulated term was num'/den with num' = num/4 -> scale by 4/Npix
    if (t == 0) out[0] = s[0] * (4.0f / 16777216.0f);
}

extern "C" void kernel_launch(void* const* d_in, const int* in_sizes, int n_in,
                              void* d_out, int out_size)
{
    const float* x   = (const float*)d_in[0];
    const float* y   = (const float*)d_in[1];
    const float* win = (const float*)d_in[2];
    float* out = (float*)d_out;

    dim3 grid(NROWT, BATCH);
    ssim_map_kernel<<<grid, 256>>>(x, y, win);
    ssim_reduce_kernel<<<1, 512>>>(out);
}